// round 2
// baseline (speedup 1.0000x reference)
#include <cuda_runtime.h>

#define NSTEPS 32

__global__ __launch_bounds__(256) void snn_fused_kernel(
    const float* __restrict__ x,    // [B,1,28,28]
    const float* __restrict__ Wc1,  // [10,1,3,3]
    const float* __restrict__ Wc2,  // [20,10,3,3]
    const float* __restrict__ Wf1,  // [100,980]
    const float* __restrict__ Wf2,  // [10,100]
    float* __restrict__ out)        // [B,10]
{
    __shared__ __align__(16) float xp[30*30];       // padded input 30x30
    __shared__ __align__(16) float p1p[10*16*16];   // padded pooled spikes (10,16,16)
    __shared__ float w1s[90];
    __shared__ float w2s[1800];
    __shared__ float wf2s[1000];
    __shared__ float zs[980];
    __shared__ float hs[100];
    __shared__ float o1s[100];
    __shared__ float cnts[10];

    const int t = threadIdx.x;
    const int b = blockIdx.x;

    // ---- init: zero padded arrays, stage weights ----
    for (int i = t; i < 900;  i += 256) xp[i]  = 0.f;
    for (int i = t; i < 2560; i += 256) p1p[i] = 0.f;
    for (int i = t; i < 90;   i += 256) w1s[i]  = Wc1[i];
    for (int i = t; i < 1800; i += 256) w2s[i]  = Wc2[i];
    for (int i = t; i < 1000; i += 256) wf2s[i] = Wf2[i];
    __syncthreads();

    // ---- stage input (interior of padded tile) ----
    const float* xb = x + (size_t)b * 784;
    for (int i = t; i < 784; i += 256) {
        int y = i / 28, c = i - y * 28;
        xp[(y + 1) * 30 + (c + 1)] = xb[i];
    }
    __syncthreads();

    // ---- phase 1: conv1(1->10) + spike + maxpool2 (spike-OR) -> p1p interior ----
    for (int idx = t; idx < 1960; idx += 256) {
        int c   = idx / 196;
        int rem = idx - c * 196;
        int py  = rem / 14, px = rem - py * 14;

        float r[4][4];
        int base = (2 * py) * 30 + 2 * px;   // even offset -> 8B aligned
        #pragma unroll
        for (int dy = 0; dy < 4; dy++) {
            float2 a  = *(const float2*)&xp[base + dy * 30];
            float2 bq = *(const float2*)&xp[base + dy * 30 + 2];
            r[dy][0] = a.x; r[dy][1] = a.y; r[dy][2] = bq.x; r[dy][3] = bq.y;
        }
        float w[9];
        #pragma unroll
        for (int k = 0; k < 9; k++) w[k] = w1s[c * 9 + k];

        bool fired = false;
        #pragma unroll
        for (int dy = 0; dy < 2; dy++)
        #pragma unroll
        for (int dx = 0; dx < 2; dx++) {
            float s = 0.f;
            #pragma unroll
            for (int ky = 0; ky < 3; ky++)
            #pragma unroll
            for (int kx = 0; kx < 3; kx++)
                s += r[dy + ky][dx + kx] * w[ky * 3 + kx];
            fired = fired || (s >= 1.0f);
        }
        p1p[c * 256 + (py + 1) * 16 + (px + 1)] = fired ? 1.f : 0.f;
    }
    __syncthreads();

    // ---- phase 2: conv2(10->20) + spike + maxpool2 -> zs[980] ----
    for (int idx = t; idx < 980; idx += 256) {
        int c   = idx / 49;
        int rem = idx - c * 49;
        int py  = rem / 7, px = rem - py * 7;

        float a00 = 0.f, a01 = 0.f, a10 = 0.f, a11 = 0.f;
        int base = (2 * py) * 16 + 2 * px;
        for (int ci = 0; ci < 10; ci++) {
            float r[4][4];
            const float* pp = &p1p[ci * 256 + base];
            #pragma unroll
            for (int dy = 0; dy < 4; dy++) {
                float2 a  = *(const float2*)&pp[dy * 16];
                float2 bq = *(const float2*)&pp[dy * 16 + 2];
                r[dy][0] = a.x; r[dy][1] = a.y; r[dy][2] = bq.x; r[dy][3] = bq.y;
            }
            const float* wp = &w2s[c * 90 + ci * 9];
            float w[9];
            #pragma unroll
            for (int k = 0; k < 9; k++) w[k] = wp[k];

            a00 += r[0][0]*w[0] + r[0][1]*w[1] + r[0][2]*w[2]
                 + r[1][0]*w[3] + r[1][1]*w[4] + r[1][2]*w[5]
                 + r[2][0]*w[6] + r[2][1]*w[7] + r[2][2]*w[8];
            a01 += r[0][1]*w[0] + r[0][2]*w[1] + r[0][3]*w[2]
                 + r[1][1]*w[3] + r[1][2]*w[4] + r[1][3]*w[5]
                 + r[2][1]*w[6] + r[2][2]*w[7] + r[2][3]*w[8];
            a10 += r[1][0]*w[0] + r[1][1]*w[1] + r[1][2]*w[2]
                 + r[2][0]*w[3] + r[2][1]*w[4] + r[2][2]*w[5]
                 + r[3][0]*w[6] + r[3][1]*w[7] + r[3][2]*w[8];
            a11 += r[1][1]*w[0] + r[1][2]*w[1] + r[1][3]*w[2]
                 + r[2][1]*w[3] + r[2][2]*w[4] + r[2][3]*w[5]
                 + r[3][1]*w[6] + r[3][2]*w[7] + r[3][3]*w[8];
        }
        bool fired = (a00 >= 1.f) || (a01 >= 1.f) || (a10 >= 1.f) || (a11 >= 1.f);
        zs[idx] = fired ? 1.f : 0.f;   // idx == c*49 + py*7 + px == flatten order
    }
    __syncthreads();

    // ---- phase 3: fc1  h[i] = sum_j Wf1[i,j] * z[j]  (warp per row, coalesced) ----
    const int warp = t >> 5, lane = t & 31;
    for (int i = warp; i < 100; i += 8) {
        const float* wr = Wf1 + (size_t)i * 980;
        float acc = 0.f;
        for (int j = lane; j < 980; j += 32)
            acc += wr[j] * zs[j];
        #pragma unroll
        for (int off = 16; off; off >>= 1)
            acc += __shfl_down_sync(0xffffffffu, acc, off);
        if (lane == 0) hs[i] = acc;
    }
    __syncthreads();

    // ---- phase 4: LIF loop, T=32 ----
    float v1 = 0.f, h = 0.f, v2 = 0.f, cnt = 0.f;
    if (t < 100) h = hs[t];
    for (int st = 0; st < NSTEPS; st++) {
        if (t < 100) {
            v1 = v1 + (h - v1) * 0.5f;
            float o = (v1 >= 1.0f) ? 1.f : 0.f;
            o1s[t] = o;
            v1 = (o != 0.f) ? 0.f : v1;
        }
        __syncthreads();
        if (t < 10) {
            float y = 0.f;
            #pragma unroll 10
            for (int i = 0; i < 100; i++)
                y += o1s[i] * wf2s[t * 100 + i];
            v2 = v2 + (y - v2) * 0.5f;
            float o = (v2 >= 1.0f) ? 1.f : 0.f;
            cnt += o;
            v2 = (o != 0.f) ? 0.f : v2;
        }
        __syncthreads();
    }

    // ---- phase 5: softmax over 10 logits ----
    if (t < 10) cnts[t] = cnt * (1.0f / 32.0f);
    __syncthreads();
    if (t < 10) {
        float m = cnts[0];
        #pragma unroll
        for (int i = 1; i < 10; i++) m = fmaxf(m, cnts[i]);
        float ssum = 0.f, mine = 0.f;
        #pragma unroll
        for (int i = 0; i < 10; i++) {
            float e = expf(cnts[i] - m);
            ssum += e;
            if (i == t) mine = e;
        }
        out[(size_t)b * 10 + t] = mine / ssum;
    }
}

extern "C" void kernel_launch(void* const* d_in, const int* in_sizes, int n_in,
                              void* d_out, int out_size) {
    const float* x   = (const float*)d_in[0];
    const float* Wc1 = (const float*)d_in[1];
    const float* Wc2 = (const float*)d_in[2];
    const float* Wf1 = (const float*)d_in[3];
    const float* Wf2 = (const float*)d_in[4];
    float* out = (float*)d_out;
    int B = in_sizes[0] / 784;
    snn_fused_kernel<<<B, 256>>>(x, Wc1, Wc2, Wf1, Wf2, out);
}

// round 3
// speedup vs baseline: 1.1599x; 1.1599x over previous
#include <cuda_runtime.h>

#define S 4
#define NSTEPS 32

__global__ __launch_bounds__(256) void snn_fused_kernel(
    const float* __restrict__ x,    // [B,1,28,28]
    const float* __restrict__ Wc1,  // [10,1,3,3]
    const float* __restrict__ Wc2,  // [20,10,3,3]
    const float* __restrict__ Wf1,  // [100,980]
    const float* __restrict__ Wf2,  // [10,100]
    float* __restrict__ out,        // [B,10]
    int B)
{
    __shared__ __align__(16) float    xp[S][900];     // padded 30x30 per sample
    __shared__ __align__(16) unsigned p1m[S][256];    // 16x16 padded, 10-bit channel mask per pixel
    __shared__ float w1s[90];
    __shared__ float w2s[1800];
    __shared__ float wf2s[1000];
    __shared__ unsigned zpack[S][32];                 // 980-bit z per sample (bits >=980 stay 0)
    __shared__ float hs[S][100];
    __shared__ unsigned o1m[2][S][4];                 // double-buffered 100-bit o1 masks
    __shared__ float cnts[S][10];

    const int t  = threadIdx.x;
    const int b0 = blockIdx.x * S;

    // ---- init ----
    for (int i = t; i < S*900; i += 256) ((float*)xp)[i] = 0.f;
    for (int i = t; i < S*256; i += 256) ((unsigned*)p1m)[i] = 0u;
    for (int i = t; i < S*32;  i += 256) ((unsigned*)zpack)[i] = 0u;
    for (int i = t; i < 90;    i += 256) w1s[i]  = Wc1[i];
    for (int i = t; i < 1800;  i += 256) w2s[i]  = Wc2[i];
    for (int i = t; i < 1000;  i += 256) wf2s[i] = Wf2[i];
    __syncthreads();

    // ---- stage inputs ----
    for (int i = t; i < S*784; i += 256) {
        int s = i / 784, j = i - s * 784;
        if (b0 + s < B) {
            int y = j / 28, c = j - y * 28;
            xp[s][(y + 1) * 30 + (c + 1)] = x[(size_t)(b0 + s) * 784 + j];
        }
    }
    __syncthreads();

    // ---- phase 1: conv1(1->10)+spike+pool -> channel bitmask per pooled pixel ----
    for (int idx = t; idx < S*196; idx += 256) {
        int s   = idx / 196;
        int pos = idx - s * 196;
        int py = pos / 14, px = pos - py * 14;

        float r[4][4];
        int base = (2 * py) * 30 + 2 * px;          // even -> 8B aligned
        #pragma unroll
        for (int dy = 0; dy < 4; dy++) {
            float2 a  = *(const float2*)&xp[s][base + dy * 30];
            float2 bq = *(const float2*)&xp[s][base + dy * 30 + 2];
            r[dy][0] = a.x; r[dy][1] = a.y; r[dy][2] = bq.x; r[dy][3] = bq.y;
        }
        unsigned mask = 0u;
        for (int c = 0; c < 10; c++) {
            const float* wp = &w1s[c * 9];
            float w[9];
            #pragma unroll
            for (int k = 0; k < 9; k++) w[k] = wp[k];
            bool fired = false;
            #pragma unroll
            for (int dy = 0; dy < 2; dy++)
            #pragma unroll
            for (int dx = 0; dx < 2; dx++) {
                float sacc = 0.f;
                #pragma unroll
                for (int ky = 0; ky < 3; ky++)
                #pragma unroll
                for (int kx = 0; kx < 3; kx++)
                    sacc += r[dy + ky][dx + kx] * w[ky * 3 + kx];
                fired = fired || (sacc >= 1.0f);
            }
            if (fired) mask |= (1u << c);
        }
        p1m[s][(py + 1) * 16 + (px + 1)] = mask;
    }
    __syncthreads();

    // ---- phase 2: conv2(10->20)+spike+pool -> z bitmap (2 out-channels per item) ----
    for (int idx = t; idx < S*10*49; idx += 256) {
        int s   = idx / 490;
        int rm  = idx - s * 490;
        int c2  = rm / 49;
        int pos = rm - c2 * 49;
        int py = pos / 7, px = pos - py * 7;

        unsigned m[4][4];
        int base = (2 * py) * 16 + 2 * px;          // even -> uint2 aligned
        unsigned orall = 0u;
        #pragma unroll
        for (int dy = 0; dy < 4; dy++) {
            const unsigned* pp = &p1m[s][base + dy * 16];
            uint2 a  = *(const uint2*)&pp[0];
            uint2 bq = *(const uint2*)&pp[2];
            m[dy][0] = a.x; m[dy][1] = a.y; m[dy][2] = bq.x; m[dy][3] = bq.y;
            orall |= a.x | a.y | bq.x | bq.y;
        }

        int cA = 2 * c2, cB = cA + 1;
        float a00A=0.f,a01A=0.f,a10A=0.f,a11A=0.f;
        float a00B=0.f,a01B=0.f,a10B=0.f,a11B=0.f;

        for (int ci = 0; ci < 10; ci++) {
            if (!((orall >> ci) & 1u)) continue;
            float r[4][4];
            #pragma unroll
            for (int dy = 0; dy < 4; dy++)
            #pragma unroll
            for (int dx = 0; dx < 4; dx++)
                r[dy][dx] = ((m[dy][dx] >> ci) & 1u) ? 1.0f : 0.0f;

            const float* wpA = &w2s[cA * 90 + ci * 9];
            const float* wpB = &w2s[cB * 90 + ci * 9];
            float wA[9], wB[9];
            #pragma unroll
            for (int k = 0; k < 9; k++) { wA[k] = wpA[k]; wB[k] = wpB[k]; }

            #pragma unroll
            for (int ky = 0; ky < 3; ky++)
            #pragma unroll
            for (int kx = 0; kx < 3; kx++) {
                int k = ky * 3 + kx;
                a00A += r[ky  ][kx  ] * wA[k];  a00B += r[ky  ][kx  ] * wB[k];
                a01A += r[ky  ][kx+1] * wA[k];  a01B += r[ky  ][kx+1] * wB[k];
                a10A += r[ky+1][kx  ] * wA[k];  a10B += r[ky+1][kx  ] * wB[k];
                a11A += r[ky+1][kx+1] * wA[k];  a11B += r[ky+1][kx+1] * wB[k];
            }
        }
        bool fA = (a00A>=1.f)||(a01A>=1.f)||(a10A>=1.f)||(a11A>=1.f);
        bool fB = (a00B>=1.f)||(a01B>=1.f)||(a10B>=1.f)||(a11B>=1.f);
        int zA = cA * 49 + pos, zB = cB * 49 + pos;
        if (fA) atomicOr(&zpack[s][zA >> 5], 1u << (zA & 31));
        if (fB) atomicOr(&zpack[s][zB >> 5], 1u << (zB & 31));
    }
    __syncthreads();

    // ---- phase 3: fc1  h[s][i] = sum_{j: z=1} Wf1[i,j]  (warp/row, broadcast bit words) ----
    const int warp = t >> 5, lane = t & 31;
    const unsigned lanebit = 1u << lane;
    for (int i = warp; i < 100; i += 8) {
        const float* wr = Wf1 + (size_t)i * 980;
        float acc0=0.f, acc1=0.f, acc2=0.f, acc3=0.f;
        #pragma unroll
        for (int k = 0; k < 30; k++) {
            float w = wr[k * 32 + lane];
            if (zpack[0][k] & lanebit) acc0 += w;
            if (zpack[1][k] & lanebit) acc1 += w;
            if (zpack[2][k] & lanebit) acc2 += w;
            if (zpack[3][k] & lanebit) acc3 += w;
        }
        {   // tail: j = 960 + lane, valid for lane < 20
            float w = (lane < 20) ? wr[960 + lane] : 0.f;
            if (zpack[0][30] & lanebit) acc0 += w;
            if (zpack[1][30] & lanebit) acc1 += w;
            if (zpack[2][30] & lanebit) acc2 += w;
            if (zpack[3][30] & lanebit) acc3 += w;
        }
        #pragma unroll
        for (int off = 16; off; off >>= 1) {
            acc0 += __shfl_down_sync(0xffffffffu, acc0, off);
            acc1 += __shfl_down_sync(0xffffffffu, acc1, off);
            acc2 += __shfl_down_sync(0xffffffffu, acc2, off);
            acc3 += __shfl_down_sync(0xffffffffu, acc3, off);
        }
        if (lane == 0) { hs[0][i]=acc0; hs[1][i]=acc1; hs[2][i]=acc2; hs[3][i]=acc3; }
    }
    __syncthreads();

    // ---- phase 4: LIF loop (writers: warps 0-3 via ballot; readers: threads 128-167) ----
    float v1[S], hv[S];
    if (t < 128) {
        #pragma unroll
        for (int s = 0; s < S; s++) { v1[s] = 0.f; hv[s] = (t < 100) ? hs[s][t] : 0.f; }
    }
    float v2 = 0.f, cnt = 0.f;
    int rs = 0, ro = 0;
    if (t >= 128 && t < 168) { rs = (t - 128) / 10; ro = (t - 128) % 10; }

    for (int st = 0; st < NSTEPS; st++) {
        int p = st & 1;
        if (t < 128) {
            #pragma unroll
            for (int s = 0; s < S; s++) {
                v1[s] = v1[s] + (hv[s] - v1[s]) * 0.5f;
                bool o = (v1[s] >= 1.0f);
                unsigned bal = __ballot_sync(0xffffffffu, o);
                if (o) v1[s] = 0.f;
                if (lane == 0) o1m[p][s][warp] = bal;
            }
        }
        __syncthreads();
        if (t >= 128 && t < 168) {
            float y = 0.f;
            #pragma unroll
            for (int w = 0; w < 4; w++) {
                unsigned mm = o1m[p][rs][w];
                #pragma unroll
                for (int bpos = 0; bpos < 32; bpos++) {
                    int i = 32 * w + bpos;
                    if (i < 100) {
                        if ((mm >> bpos) & 1u) y += wf2s[ro * 100 + i];
                    }
                }
            }
            v2 = v2 + (y - v2) * 0.5f;
            if (v2 >= 1.0f) { cnt += 1.0f; v2 = 0.f; }
        }
        // no second sync: double-buffered o1m
    }
    if (t >= 128 && t < 168) cnts[rs][ro] = cnt * (1.0f / 32.0f);
    __syncthreads();

    // ---- phase 5: softmax ----
    if (t < 40) {
        int s = t / 10, o = t - (t / 10) * 10;
        if (b0 + s < B) {
            float mx = cnts[s][0];
            #pragma unroll
            for (int i = 1; i < 10; i++) mx = fmaxf(mx, cnts[s][i]);
            float ssum = 0.f, mine = 0.f;
            #pragma unroll
            for (int i = 0; i < 10; i++) {
                float e = expf(cnts[s][i] - mx);
                ssum += e;
                if (i == o) mine = e;
            }
            out[(size_t)(b0 + s) * 10 + o] = mine / ssum;
        }
    }
}

extern "C" void kernel_launch(void* const* d_in, const int* in_sizes, int n_in,
                              void* d_out, int out_size) {
    const float* x   = (const float*)d_in[0];
    const float* Wc1 = (const float*)d_in[1];
    const float* Wc2 = (const float*)d_in[2];
    const float* Wf1 = (const float*)d_in[3];
    const float* Wf2 = (const float*)d_in[4];
    float* out = (float*)d_out;
    int B = in_sizes[0] / 784;
    int grid = (B + S - 1) / S;
    snn_fused_kernel<<<grid, 256>>>(x, Wc1, Wc2, Wf1, Wf2, out, B);
}

// round 4
// speedup vs baseline: 1.9171x; 1.6528x over previous
#include <cuda_runtime.h>

#define S 4
#define NSTEPS 32

typedef unsigned long long ull;

__device__ __forceinline__ ull pk2(float lo, float hi) {
    ull r; asm("mov.b64 %0,{%1,%2};" : "=l"(r) : "f"(lo), "f"(hi)); return r;
}
__device__ __forceinline__ void upk2(ull v, float& lo, float& hi) {
    asm("mov.b64 {%0,%1},%2;" : "=f"(lo), "=f"(hi) : "l"(v));
}
__device__ __forceinline__ void fma2(ull& d, ull a, ull b) {
    asm("fma.rn.f32x2 %0,%1,%2,%3;" : "=l"(d) : "l"(a), "l"(b), "l"(d));
}

__global__ __launch_bounds__(256, 2) void snn_fused_kernel(
    const float* __restrict__ x,    // [B,1,28,28]
    const float* __restrict__ Wc1,  // [10,1,3,3]
    const float* __restrict__ Wc2,  // [20,10,3,3]
    const float* __restrict__ Wf1,  // [100,980]
    const float* __restrict__ Wf2,  // [10,100]
    float* __restrict__ out,        // [B,10]
    int B)
{
    __shared__ __align__(16) float    xp[S][900];    // padded 30x30 per sample
    __shared__ __align__(16) unsigned p1m[S][256];   // 16x16 padded, 10-bit channel mask
    __shared__ ull   w1p[45];          // [cp][k] packed (w[2cp][k], w[2cp+1][k])
    __shared__ ull   w2p[900];         // [cp2*10+ci][k] packed pairs
    __shared__ float wf2s[1000];
    __shared__ __align__(16) float4 zs4[1024];       // z over 4 samples, padded
    __shared__ float hs[S][100];
    __shared__ unsigned o1m[2][S][4];  // double-buffered 100-bit o1 masks
    __shared__ float cnts[S][10];

    const int t  = threadIdx.x;
    const int b0 = blockIdx.x * S;
    const int warp = t >> 5, lane = t & 31;

    // ---- init ----
    for (int i = t; i < S*900; i += 256) ((float*)xp)[i] = 0.f;
    for (int i = t; i < S*256; i += 256) ((unsigned*)p1m)[i] = 0u;
    for (int i = t; i < 45; i += 256) {
        int cp = i / 9, k = i - cp * 9;
        w1p[i] = pk2(Wc1[(2*cp)*9 + k], Wc1[(2*cp+1)*9 + k]);
    }
    for (int i = t; i < 900; i += 256) {
        int cp2 = i / 90, rem = i - cp2 * 90;
        int ci = rem / 9, k = rem - ci * 9;
        w2p[i] = pk2(Wc2[(2*cp2)*90 + ci*9 + k], Wc2[(2*cp2+1)*90 + ci*9 + k]);
    }
    for (int i = t; i < 1000; i += 256) wf2s[i] = Wf2[i];
    for (int i = 980 + t; i < 1024; i += 256) zs4[i] = make_float4(0.f,0.f,0.f,0.f);
    __syncthreads();

    // ---- stage inputs ----
    for (int i = t; i < S*784; i += 256) {
        int s = i / 784, j = i - s * 784;
        if (b0 + s < B) {
            int y = j / 28, c = j - y * 28;
            xp[s][(y + 1) * 30 + (c + 1)] = x[(size_t)(b0 + s) * 784 + j];
        }
    }
    __syncthreads();

    // ---- phase 1: conv1(1->10)+spike+pool, f32x2 packed over 5 channel-pairs ----
    for (int idx = t; idx < S*196; idx += 256) {
        int s   = idx / 196;
        int pos = idx - s * 196;
        int py = pos / 14, px = pos - py * 14;

        ull rr[4][4];
        {
            int base = (2 * py) * 30 + 2 * px;   // even -> 8B aligned
            #pragma unroll
            for (int dy = 0; dy < 4; dy++) {
                float2 a  = *(const float2*)&xp[s][base + dy * 30];
                float2 bq = *(const float2*)&xp[s][base + dy * 30 + 2];
                rr[dy][0] = pk2(a.x, a.x); rr[dy][1] = pk2(a.y, a.y);
                rr[dy][2] = pk2(bq.x, bq.x); rr[dy][3] = pk2(bq.y, bq.y);
            }
        }
        ull acc[5][4];
        #pragma unroll
        for (int q = 0; q < 5; q++)
            #pragma unroll
            for (int p = 0; p < 4; p++) acc[q][p] = 0ULL;

        #pragma unroll
        for (int ky = 0; ky < 3; ky++)
        #pragma unroll
        for (int kx = 0; kx < 3; kx++) {
            int k = ky * 3 + kx;
            #pragma unroll
            for (int q = 0; q < 5; q++) {
                ull wp = w1p[q * 9 + k];
                fma2(acc[q][0], rr[ky  ][kx  ], wp);
                fma2(acc[q][1], rr[ky  ][kx+1], wp);
                fma2(acc[q][2], rr[ky+1][kx  ], wp);
                fma2(acc[q][3], rr[ky+1][kx+1], wp);
            }
        }
        unsigned mask = 0u;
        #pragma unroll
        for (int q = 0; q < 5; q++) {
            float a0,b0v,a1,b1v,a2,b2v,a3,b3v;
            upk2(acc[q][0], a0, b0v); upk2(acc[q][1], a1, b1v);
            upk2(acc[q][2], a2, b2v); upk2(acc[q][3], a3, b3v);
            float mA = fmaxf(fmaxf(a0, a1), fmaxf(a2, a3));
            float mB = fmaxf(fmaxf(b0v, b1v), fmaxf(b2v, b3v));
            if (mA >= 1.0f) mask |= (1u << (2*q));
            if (mB >= 1.0f) mask |= (1u << (2*q+1));
        }
        p1m[s][(py + 1) * 16 + (px + 1)] = mask;
    }
    __syncthreads();

    // ---- phase 2: conv2(10->20)+spike+pool, f32x2 packed; item=(s,pos,half) ----
    for (int idx = t; idx < S*2*49; idx += 256) {
        int s    = idx / 98;
        int rem  = idx - s * 98;
        int half = rem / 49;
        int pos  = rem - half * 49;
        int py = pos / 7, px = pos - py * 7;

        unsigned m[4][4];
        {
            int base = (2 * py) * 16 + 2 * px;   // even -> uint2 aligned
            #pragma unroll
            for (int dy = 0; dy < 4; dy++) {
                const unsigned* pp = &p1m[s][base + dy * 16];
                uint2 a  = *(const uint2*)&pp[0];
                uint2 bq = *(const uint2*)&pp[2];
                m[dy][0] = a.x; m[dy][1] = a.y; m[dy][2] = bq.x; m[dy][3] = bq.y;
            }
        }
        ull acc[5][4];
        #pragma unroll
        for (int q = 0; q < 5; q++)
            #pragma unroll
            for (int p = 0; p < 4; p++) acc[q][p] = 0ULL;

        #pragma unroll 1
        for (int ci = 0; ci < 10; ci++) {
            ull rr[4][4];
            #pragma unroll
            for (int dy = 0; dy < 4; dy++)
            #pragma unroll
            for (int dx = 0; dx < 4; dx++) {
                float f = ((m[dy][dx] >> ci) & 1u) ? 1.0f : 0.0f;
                rr[dy][dx] = pk2(f, f);
            }
            const ull* wb = &w2p[((half * 5) * 10 + ci) * 9];  // +q*90 per pair
            #pragma unroll
            for (int ky = 0; ky < 3; ky++)
            #pragma unroll
            for (int kx = 0; kx < 3; kx++) {
                int k = ky * 3 + kx;
                #pragma unroll
                for (int q = 0; q < 5; q++) {
                    ull wp = wb[q * 90 + k];
                    fma2(acc[q][0], rr[ky  ][kx  ], wp);
                    fma2(acc[q][1], rr[ky  ][kx+1], wp);
                    fma2(acc[q][2], rr[ky+1][kx  ], wp);
                    fma2(acc[q][3], rr[ky+1][kx+1], wp);
                }
            }
        }
        #pragma unroll
        for (int q = 0; q < 5; q++) {
            float a0,c0,a1,c1,a2,c2,a3,c3;
            upk2(acc[q][0], a0, c0); upk2(acc[q][1], a1, c1);
            upk2(acc[q][2], a2, c2); upk2(acc[q][3], a3, c3);
            float mA = fmaxf(fmaxf(a0, a1), fmaxf(a2, a3));
            float mB = fmaxf(fmaxf(c0, c1), fmaxf(c2, c3));
            int cA = 10 * half + 2 * q;
            ((float*)&zs4[cA * 49 + pos])[s]       = (mA >= 1.0f) ? 1.0f : 0.0f;
            ((float*)&zs4[(cA + 1) * 49 + pos])[s] = (mB >= 1.0f) ? 1.0f : 0.0f;
        }
    }
    __syncthreads();

    // ---- phase 3: fc1  h[s][i] = Wf1[i,:] . z[s]  (warp/row, float4 over samples) ----
    for (int i = warp; i < 100; i += 8) {
        const float* wr = Wf1 + (size_t)i * 980;
        float a0 = 0.f, a1 = 0.f, a2 = 0.f, a3 = 0.f;
        #pragma unroll 5
        for (int k = 0; k < 30; k++) {
            float w = wr[k * 32 + lane];
            float4 z = zs4[k * 32 + lane];
            a0 = fmaf(w, z.x, a0);
            a1 = fmaf(w, z.y, a1);
            a2 = fmaf(w, z.z, a2);
            a3 = fmaf(w, z.w, a3);
        }
        {   // tail: j = 960 + lane, valid for lane < 20 (pad z is zeroed)
            float w = (lane < 20) ? wr[960 + lane] : 0.f;
            float4 z = zs4[960 + lane];
            a0 = fmaf(w, z.x, a0);
            a1 = fmaf(w, z.y, a1);
            a2 = fmaf(w, z.z, a2);
            a3 = fmaf(w, z.w, a3);
        }
        #pragma unroll
        for (int off = 16; off; off >>= 1) {
            a0 += __shfl_down_sync(0xffffffffu, a0, off);
            a1 += __shfl_down_sync(0xffffffffu, a1, off);
            a2 += __shfl_down_sync(0xffffffffu, a2, off);
            a3 += __shfl_down_sync(0xffffffffu, a3, off);
        }
        if (lane == 0) { hs[0][i]=a0; hs[1][i]=a1; hs[2][i]=a2; hs[3][i]=a3; }
    }
    __syncthreads();

    // ---- phase 4: LIF loop (writers warps 0-3 via ballot; readers t in [128,168)) ----
    float v1[S], hv[S];
    if (t < 128) {
        #pragma unroll
        for (int s = 0; s < S; s++) { v1[s] = 0.f; hv[s] = (t < 100) ? hs[s][t] : 0.f; }
    }
    float v2 = 0.f, cnt = 0.f;
    int rs = 0, ro = 0;
    if (t >= 128 && t < 168) { rs = (t - 128) / 10; ro = (t - 128) % 10; }

    for (int st = 0; st < NSTEPS; st++) {
        int p = st & 1;
        if (t < 128) {
            #pragma unroll
            for (int s = 0; s < S; s++) {
                v1[s] = v1[s] + (hv[s] - v1[s]) * 0.5f;
                bool o = (v1[s] >= 1.0f);
                unsigned bal = __ballot_sync(0xffffffffu, o);
                if (o) v1[s] = 0.f;
                if (lane == 0) o1m[p][s][warp] = bal;
            }
        }
        __syncthreads();
        if (t >= 128 && t < 168) {
            float y = 0.f;
            #pragma unroll
            for (int w = 0; w < 4; w++) {
                unsigned mm = o1m[p][rs][w];
                #pragma unroll
                for (int bpos = 0; bpos < 32; bpos++) {
                    int i = 32 * w + bpos;
                    if (i < 100) {
                        if ((mm >> bpos) & 1u) y += wf2s[ro * 100 + i];
                    }
                }
            }
            v2 = v2 + (y - v2) * 0.5f;
            if (v2 >= 1.0f) { cnt += 1.0f; v2 = 0.f; }
        }
        // no second sync: double-buffered o1m
    }
    if (t >= 128 && t < 168) cnts[rs][ro] = cnt * (1.0f / 32.0f);
    __syncthreads();

    // ---- phase 5: softmax ----
    if (t < 40) {
        int s = t / 10, o = t - (t / 10) * 10;
        if (b0 + s < B) {
            float mx = cnts[s][0];
            #pragma unroll
            for (int i = 1; i < 10; i++) mx = fmaxf(mx, cnts[s][i]);
            float ssum = 0.f, mine = 0.f;
            #pragma unroll
            for (int i = 0; i < 10; i++) {
                float e = expf(cnts[s][i] - mx);
                ssum += e;
                if (i == o) mine = e;
            }
            out[(size_t)(b0 + s) * 10 + o] = mine / ssum;
        }
    }
}

extern "C" void kernel_launch(void* const* d_in, const int* in_sizes, int n_in,
                              void* d_out, int out_size) {
    const float* x   = (const float*)d_in[0];
    const float* Wc1 = (const float*)d_in[1];
    const float* Wc2 = (const float*)d_in[2];
    const float* Wf1 = (const float*)d_in[3];
    const float* Wf2 = (const float*)d_in[4];
    float* out = (float*)d_out;
    int B = in_sizes[0] / 784;
    int grid = (B + S - 1) / S;
    snn_fused_kernel<<<grid, 256>>>(x, Wc1, Wc2, Wf1, Wf2, out, B);
}

// round 7
// speedup vs baseline: 2.4267x; 1.2658x over previous
#include <cuda_runtime.h>

#define S 8
#define NSTEPS 32

typedef unsigned long long ull;

__device__ __forceinline__ ull pk2(float lo, float hi) {
    ull r; asm("mov.b64 %0,{%1,%2};" : "=l"(r) : "f"(lo), "f"(hi)); return r;
}
__device__ __forceinline__ void upk2(ull v, float& lo, float& hi) {
    asm("mov.b64 {%0,%1},%2;" : "=f"(lo), "=f"(hi) : "l"(v));
}
__device__ __forceinline__ void fma2(ull& d, ull a, ull b) {
    asm("fma.rn.f32x2 %0,%1,%2,%3;" : "=l"(d) : "l"(a), "l"(b), "l"(d));
}

struct __align__(16) Smem {
    char uA[33 * 1024];          // xp[S][900] -> zp[1024][4] -> spkw[S][104] + Y
    unsigned p1m[S][256];        // 16x16 padded, 10-bit channel mask
    ull w1p[45];                 // conv1 weights, channel pairs
    ull w2p[900];                // conv2 weights, channel pairs
    __align__(16) ull wf2p[100][6];  // fc2 weights, o-pairs (pad [5]=0); 16B-aligned for ulonglong2 loads
    float hs[S][100];
    float cnts[S][10];
};

__global__ __launch_bounds__(256, 2) void snn_fused_kernel(
    const float* __restrict__ x,    // [B,1,28,28]
    const float* __restrict__ Wc1,  // [10,1,3,3]
    const float* __restrict__ Wc2,  // [20,10,3,3]
    const float* __restrict__ Wf1,  // [100,980]
    const float* __restrict__ Wf2,  // [10,100]
    float* __restrict__ out,        // [B,10]
    int B)
{
    extern __shared__ __align__(16) char smem_raw[];
    Smem* sm = (Smem*)smem_raw;

    float*    xp   = (float*)sm->uA;            // [S][900]
    ull*      zp   = (ull*)sm->uA;              // [1024][4]  (pairs of samples)
    unsigned* spkw = (unsigned*)sm->uA;         // [S][104]
    float*    Y    = (float*)(sm->uA + 4096);   // [S*10][33]

    const int t  = threadIdx.x;
    const int b0 = blockIdx.x * S;
    const int warp = t >> 5, lane = t & 31;

    // ---- init ----
    for (int i = t; i < S * 900; i += 256) xp[i] = 0.f;
    for (int i = t; i < S * 256; i += 256) ((unsigned*)sm->p1m)[i] = 0u;
    for (int i = t; i < 45; i += 256) {
        int cp = i / 9, k = i - cp * 9;
        sm->w1p[i] = pk2(Wc1[(2 * cp) * 9 + k], Wc1[(2 * cp + 1) * 9 + k]);
    }
    for (int i = t; i < 900; i += 256) {
        int cp2 = i / 90, rem = i - cp2 * 90;
        int ci = rem / 9, k = rem - ci * 9;
        sm->w2p[i] = pk2(Wc2[(2 * cp2) * 90 + ci * 9 + k], Wc2[(2 * cp2 + 1) * 90 + ci * 9 + k]);
    }
    for (int i = t; i < 600; i += 256) {
        int ii = i / 6, q = i - (i / 6) * 6;
        sm->wf2p[ii][q] = (q < 5) ? pk2(Wf2[(2 * q) * 100 + ii], Wf2[(2 * q + 1) * 100 + ii]) : 0ULL;
    }
    __syncthreads();

    // ---- stage inputs ----
    for (int i = t; i < S * 784; i += 256) {
        int s = i / 784, j = i - s * 784;
        if (b0 + s < B) {
            int y = j / 28, c = j - y * 28;
            xp[s * 900 + (y + 1) * 30 + (c + 1)] = x[(size_t)(b0 + s) * 784 + j];
        }
    }
    __syncthreads();

    // ---- phase 1: conv1(1->10)+spike+pool, f32x2 over 5 channel pairs ----
    for (int idx = t; idx < S * 196; idx += 256) {
        int s   = idx / 196;
        int pos = idx - s * 196;
        int py = pos / 14, px = pos - py * 14;

        ull rr[4][4];
        {
            int base = s * 900 + (2 * py) * 30 + 2 * px;   // even -> 8B aligned
            #pragma unroll
            for (int dy = 0; dy < 4; dy++) {
                float2 a  = *(const float2*)&xp[base + dy * 30];
                float2 bq = *(const float2*)&xp[base + dy * 30 + 2];
                rr[dy][0] = pk2(a.x, a.x);  rr[dy][1] = pk2(a.y, a.y);
                rr[dy][2] = pk2(bq.x, bq.x); rr[dy][3] = pk2(bq.y, bq.y);
            }
        }
        ull acc[5][4];
        #pragma unroll
        for (int q = 0; q < 5; q++)
            #pragma unroll
            for (int p = 0; p < 4; p++) acc[q][p] = 0ULL;

        #pragma unroll
        for (int ky = 0; ky < 3; ky++)
        #pragma unroll
        for (int kx = 0; kx < 3; kx++) {
            int k = ky * 3 + kx;
            #pragma unroll
            for (int q = 0; q < 5; q++) {
                ull wp = sm->w1p[q * 9 + k];
                fma2(acc[q][0], rr[ky  ][kx  ], wp);
                fma2(acc[q][1], rr[ky  ][kx+1], wp);
                fma2(acc[q][2], rr[ky+1][kx  ], wp);
                fma2(acc[q][3], rr[ky+1][kx+1], wp);
            }
        }
        unsigned mask = 0u;
        #pragma unroll
        for (int q = 0; q < 5; q++) {
            float a0,b0v,a1,b1v,a2,b2v,a3,b3v;
            upk2(acc[q][0], a0, b0v); upk2(acc[q][1], a1, b1v);
            upk2(acc[q][2], a2, b2v); upk2(acc[q][3], a3, b3v);
            float mA = fmaxf(fmaxf(a0, a1), fmaxf(a2, a3));
            float mB = fmaxf(fmaxf(b0v, b1v), fmaxf(b2v, b3v));
            if (mA >= 1.0f) mask |= (1u << (2 * q));
            if (mB >= 1.0f) mask |= (1u << (2 * q + 1));
        }
        sm->p1m[s][(py + 1) * 16 + (px + 1)] = mask;
    }
    __syncthreads();

    // ---- phase 2: conv2(10->20)+spike+pool -> zp pairs ----
    // zero the fc1 pad region of zp (bytes beyond old xp extent may be garbage)
    for (int i = 980 * 4 + t; i < 1024 * 4; i += 256) zp[i] = 0ULL;

    for (int idx = t; idx < S * 2 * 49; idx += 256) {
        int s    = idx / 98;
        int rem  = idx - s * 98;
        int half = rem / 49;
        int pos  = rem - half * 49;
        int py = pos / 7, px = pos - py * 7;

        unsigned m[4][4];
        {
            int base = (2 * py) * 16 + 2 * px;   // even -> uint2 aligned
            #pragma unroll
            for (int dy = 0; dy < 4; dy++) {
                const unsigned* pp = &sm->p1m[s][base + dy * 16];
                uint2 a  = *(const uint2*)&pp[0];
                uint2 bq = *(const uint2*)&pp[2];
                m[dy][0] = a.x; m[dy][1] = a.y; m[dy][2] = bq.x; m[dy][3] = bq.y;
            }
        }
        ull acc[5][4];
        #pragma unroll
        for (int q = 0; q < 5; q++)
            #pragma unroll
            for (int p = 0; p < 4; p++) acc[q][p] = 0ULL;

        #pragma unroll 1
        for (int ci = 0; ci < 10; ci++) {
            ull rr[4][4];
            #pragma unroll
            for (int dy = 0; dy < 4; dy++)
            #pragma unroll
            for (int dx = 0; dx < 4; dx++) {
                float f = (float)((m[dy][dx] >> ci) & 1u);
                rr[dy][dx] = pk2(f, f);
            }
            const ull* wb = &sm->w2p[(half * 5) * 90 + ci * 9];  // +q*90 per pair
            #pragma unroll
            for (int ky = 0; ky < 3; ky++)
            #pragma unroll
            for (int kx = 0; kx < 3; kx++) {
                int k = ky * 3 + kx;
                #pragma unroll
                for (int q = 0; q < 5; q++) {
                    ull wp = wb[q * 90 + k];
                    fma2(acc[q][0], rr[ky  ][kx  ], wp);
                    fma2(acc[q][1], rr[ky  ][kx+1], wp);
                    fma2(acc[q][2], rr[ky+1][kx  ], wp);
                    fma2(acc[q][3], rr[ky+1][kx+1], wp);
                }
            }
        }
        int pair = s >> 1, half32 = s & 1;
        #pragma unroll
        for (int q = 0; q < 5; q++) {
            float a0,c0,a1,c1,a2,c2,a3,c3;
            upk2(acc[q][0], a0, c0); upk2(acc[q][1], a1, c1);
            upk2(acc[q][2], a2, c2); upk2(acc[q][3], a3, c3);
            float mA = fmaxf(fmaxf(a0, a1), fmaxf(a2, a3));
            float mB = fmaxf(fmaxf(c0, c1), fmaxf(c2, c3));
            int cA = 10 * half + 2 * q;
            int zA = cA * 49 + pos, zB = zA + 49;
            ((float*)&zp[zA * 4 + pair])[half32] = (mA >= 1.0f) ? 1.0f : 0.0f;
            ((float*)&zp[zB * 4 + pair])[half32] = (mB >= 1.0f) ? 1.0f : 0.0f;
        }
    }
    __syncthreads();

    // ---- phase 3: fc1 (warp/row, fma2 over 4 sample-pairs) ----
    for (int i = warp; i < 100; i += 8) {
        const float* wr = Wf1 + (size_t)i * 980;
        ull a0 = 0, a1 = 0, a2 = 0, a3 = 0;
        #pragma unroll 5
        for (int k = 0; k < 30; k++) {
            float w = wr[k * 32 + lane];
            ull wp = pk2(w, w);
            const ull* zr = &zp[(k * 32 + lane) * 4];
            ulonglong2 zA = *(const ulonglong2*)zr;
            ulonglong2 zB = *(const ulonglong2*)(zr + 2);
            fma2(a0, zA.x, wp); fma2(a1, zA.y, wp);
            fma2(a2, zB.x, wp); fma2(a3, zB.y, wp);
        }
        {   // tail: j = 960 + lane (z pad is zeroed; guard w to stay in-bounds)
            float w = (lane < 20) ? wr[960 + lane] : 0.f;
            ull wp = pk2(w, w);
            const ull* zr = &zp[(960 + lane) * 4];
            ulonglong2 zA = *(const ulonglong2*)zr;
            ulonglong2 zB = *(const ulonglong2*)(zr + 2);
            fma2(a0, zA.x, wp); fma2(a1, zA.y, wp);
            fma2(a2, zB.x, wp); fma2(a3, zB.y, wp);
        }
        float f[8];
        upk2(a0, f[0], f[1]); upk2(a1, f[2], f[3]);
        upk2(a2, f[4], f[5]); upk2(a3, f[6], f[7]);
        #pragma unroll
        for (int off = 16; off; off >>= 1) {
            #pragma unroll
            for (int s2 = 0; s2 < 8; s2++)
                f[s2] += __shfl_down_sync(0xffffffffu, f[s2], off);
        }
        if (lane == 0) {
            #pragma unroll
            for (int s2 = 0; s2 < 8; s2++) sm->hs[s2][i] = f[s2];
        }
    }
    __syncthreads();

    // ---- stage A: per-neuron LIF-1 sim -> 32-bit spike train word ----
    for (int idx = t; idx < S * 100; idx += 256) {
        int s = idx & 7, i = idx >> 3;
        float h = sm->hs[s][i], v = 0.f;
        unsigned word = 0u;
        #pragma unroll
        for (int st = 0; st < NSTEPS; st++) {
            v = v + (h - v) * 0.5f;
            if (v >= 1.0f) { word |= (1u << st); v = 0.f; }
        }
        spkw[s * 104 + i] = word;
    }
    __syncthreads();

    // ---- stage B: Y[s][t][o] = sum_i spike * Wf2  (thread = (s=warp, t=lane)) ----
    {
        int s = warp;
        ull y0 = 0, y1 = 0, y2 = 0, y3 = 0, y4 = 0;
        #pragma unroll 4
        for (int i = 0; i < 100; i++) {
            unsigned wbits = spkw[s * 104 + i];
            float fsp = (float)((wbits >> lane) & 1u);
            ull fp = pk2(fsp, fsp);
            const ull* wpr = sm->wf2p[i];
            ulonglong2 wA = *(const ulonglong2*)wpr;
            ulonglong2 wB = *(const ulonglong2*)(wpr + 2);
            ull w4 = wpr[4];
            fma2(y0, fp, wA.x); fma2(y1, fp, wA.y);
            fma2(y2, fp, wB.x); fma2(y3, fp, wB.y);
            fma2(y4, fp, w4);
        }
        float yo[10];
        upk2(y0, yo[0], yo[1]); upk2(y1, yo[2], yo[3]);
        upk2(y2, yo[4], yo[5]); upk2(y3, yo[6], yo[7]);
        upk2(y4, yo[8], yo[9]);
        #pragma unroll
        for (int o = 0; o < 10; o++) Y[(s * 10 + o) * 33 + lane] = yo[o];
    }
    __syncthreads();

    // ---- stage C: LIF-2 scan over t, then softmax ----
    if (t < S * 10) {
        int s = t / 10, o = t - (t / 10) * 10;
        float v2 = 0.f, cnt = 0.f;
        const float* yr = &Y[(s * 10 + o) * 33];
        #pragma unroll
        for (int st = 0; st < NSTEPS; st++) {
            float yv = yr[st];
            v2 = v2 + (yv - v2) * 0.5f;
            if (v2 >= 1.0f) { cnt += 1.0f; v2 = 0.f; }
        }
        sm->cnts[s][o] = cnt * (1.0f / 32.0f);
    }
    __syncthreads();

    if (t < S * 10) {
        int s = t / 10, o = t - (t / 10) * 10;
        if (b0 + s < B) {
            float mx = sm->cnts[s][0];
            #pragma unroll
            for (int i = 1; i < 10; i++) mx = fmaxf(mx, sm->cnts[s][i]);
            float ssum = 0.f, mine = 0.f;
            #pragma unroll
            for (int i = 0; i < 10; i++) {
                float e = expf(sm->cnts[s][i] - mx);
                ssum += e;
                if (i == o) mine = e;
            }
            out[(size_t)(b0 + s) * 10 + o] = mine / ssum;
        }
    }
}

extern "C" void kernel_launch(void* const* d_in, const int* in_sizes, int n_in,
                              void* d_out, int out_size) {
    const float* x   = (const float*)d_in[0];
    const float* Wc1 = (const float*)d_in[1];
    const float* Wc2 = (const float*)d_in[2];
    const float* Wf1 = (const float*)d_in[3];
    const float* Wf2 = (const float*)d_in[4];
    float* out = (float*)d_out;
    int B = in_sizes[0] / 784;
    int grid = (B + S - 1) / S;
    size_t smem = sizeof(Smem);
    cudaFuncSetAttribute(snn_fused_kernel,
                         cudaFuncAttributeMaxDynamicSharedMemorySize, (int)smem);
    snn_fused_kernel<<<grid, 256, smem>>>(x, Wc1, Wc2, Wf1, Wf2, out, B);
}